// round 7
// baseline (speedup 1.0000x reference)
#include <cuda_runtime.h>
#include <math.h>
#include <stdint.h>

#define BATCH  2
#define SEQ    2048
#define DM     1024
#define NHEADS 16
#define HD     64
#define MTOT   (BATCH * SEQ)   // 4096

// ---------------- scratch (static device globals; no runtime alloc) --------
__device__ float g_q[MTOT * DM];
__device__ float g_k[MTOT * DM];
__device__ float g_v[MTOT * DM];
__device__ float g_ctx[MTOT * DM];
__device__ float g_xr[MTOT * DM];     // x rounded to tf32
__device__ float g_wt[4 * DM * DM];   // transposed tf32-rounded weights [N][K]

// ============================ helpers ======================================
__device__ __forceinline__ float tf32r(float x) {
    uint32_t r;
    asm("cvt.rna.tf32.f32 %0, %1;" : "=r"(r) : "f"(x));
    return __uint_as_float(r);
}
__device__ __forceinline__ uint32_t fu(float x) { return __float_as_uint(x); }
__device__ __forceinline__ uint32_t smem_u32(const void* p) {
    uint32_t a;
    asm("{ .reg .u64 t; cvta.to.shared.u64 t, %1; cvt.u32.u64 %0, t; }"
        : "=r"(a) : "l"(p));
    return a;
}
__device__ __forceinline__ void cpa16(uint32_t s, const void* g) {
    asm volatile("cp.async.ca.shared.global [%0], [%1], 16;" :: "r"(s), "l"(g));
}
#define CP_COMMIT() asm volatile("cp.async.commit_group;" ::: "memory")
#define CP_WAIT1()  asm volatile("cp.async.wait_group 1;" ::: "memory")

// D += A(16x8, row) * B(8x8, col), tf32 inputs, fp32 accum
__device__ __forceinline__ void mma8(float d[4], uint32_t a0, uint32_t a1,
                                     uint32_t a2, uint32_t a3,
                                     uint32_t b0, uint32_t b1) {
    asm volatile(
        "mma.sync.aligned.m16n8k8.row.col.f32.tf32.tf32.f32 "
        "{%0,%1,%2,%3}, {%4,%5,%6,%7}, {%8,%9}, {%0,%1,%2,%3};"
        : "+f"(d[0]), "+f"(d[1]), "+f"(d[2]), "+f"(d[3])
        : "r"(a0), "r"(a1), "r"(a2), "r"(a3), "r"(b0), "r"(b1));
}

// ================= prep kernels ============================================
__global__ __launch_bounds__(256) void round_x(const float* __restrict__ x) {
    int i = blockIdx.x * 256 + threadIdx.x;
    float4 v = ((const float4*)x)[i];
    v.x = tf32r(v.x); v.y = tf32r(v.y); v.z = tf32r(v.z); v.w = tf32r(v.w);
    ((float4*)g_xr)[i] = v;
}

__global__ __launch_bounds__(256) void transpose4(
    const float* __restrict__ W0, const float* __restrict__ W1,
    const float* __restrict__ W2, const float* __restrict__ W3)
{
    __shared__ float t[32][33];
    const float* src = (blockIdx.z == 0) ? W0 : (blockIdx.z == 1) ? W1
                     : (blockIdx.z == 2) ? W2 : W3;
    float* dst = g_wt + (size_t)blockIdx.z * DM * DM;
    int bk = blockIdx.y * 32, bn = blockIdx.x * 32;
    int tx = threadIdx.x & 31, ty = threadIdx.x >> 5;
#pragma unroll
    for (int i = 0; i < 4; i++)
        t[ty + 8 * i][tx] = tf32r(src[(size_t)(bk + ty + 8 * i) * DM + bn + tx]);
    __syncthreads();
#pragma unroll
    for (int i = 0; i < 4; i++)
        dst[(size_t)(bn + ty + 8 * i) * DM + bk + tx] = t[tx][ty + 8 * i];
}

// ====== tf32 mma.sync GEMM with cp.async 2-stage pipeline (unchanged) ======
#define GBM 128
#define GBN 128
#define GBK 32
#define TILE_F (128 * 36)
#define GSMEM  (2 * 2 * TILE_F * 4)

template<bool ROUND_OUT, bool HAS_BIAS, bool QKV>
__global__ __launch_bounds__(256, 2) void gemm_cp(
    const float* __restrict__ A, const float* __restrict__ BtBase,
    float* __restrict__ Cbase, const float* __restrict__ bias)
{
    extern __shared__ float gsm[];

    const int tid = threadIdx.x;
    const int warp = tid >> 5, lane = tid & 31;
    const int g = lane >> 2, t = lane & 3;
    const int wm = (warp >> 2) * 64;
    const int wn = (warp & 3) * 32;
    const int m0 = blockIdx.y * GBM;
    const int n_glob = blockIdx.x * GBN;

    const float* Bt = BtBase + (size_t)n_glob * DM;
    float* C;
    int c0;
    if (QKV) {
        int mat = n_glob >> 10;
        C = (mat == 0) ? g_q : (mat == 1) ? g_k : g_v;
        c0 = n_glob & 1023;
    } else {
        C = Cbase;
        c0 = n_glob;
    }

    const uint32_t sbase = smem_u32(gsm);
    int lrow[4], lc4[4];
#pragma unroll
    for (int it = 0; it < 4; it++) {
        int idx = tid + it * 256;
        lrow[it] = idx >> 3;
        lc4[it]  = (idx & 7) << 2;
    }

#pragma unroll
    for (int st = 0; st < 2; st++) {
        int kt = st * GBK;
        uint32_t sa = sbase + (st * 2 * TILE_F) * 4;
        uint32_t sb = sa + TILE_F * 4;
#pragma unroll
        for (int it = 0; it < 4; it++) {
            cpa16(sa + (lrow[it] * 36 + lc4[it]) * 4,
                  &A[(size_t)(m0 + lrow[it]) * DM + kt + lc4[it]]);
            cpa16(sb + (lrow[it] * 36 + lc4[it]) * 4,
                  &Bt[(size_t)lrow[it] * DM + kt + lc4[it]]);
        }
        CP_COMMIT();
    }

    float acc[4][4][4] = {};

    const int NK = DM / GBK;
    for (int i = 0; i < NK; i++) {
        CP_WAIT1();
        __syncthreads();
        const int st = i & 1;
        const float* Ast = gsm + st * 2 * TILE_F;
        const float* Bst = Ast + TILE_F;

#pragma unroll
        for (int ks = 0; ks < 4; ks++) {
            const int k8 = ks * 8;
            uint32_t af[4][4];
#pragma unroll
            for (int mt = 0; mt < 4; mt++) {
                int ar = wm + mt * 16;
                af[mt][0] = fu(Ast[(ar + g) * 36 + k8 + t]);
                af[mt][1] = fu(Ast[(ar + g + 8) * 36 + k8 + t]);
                af[mt][2] = fu(Ast[(ar + g) * 36 + k8 + t + 4]);
                af[mt][3] = fu(Ast[(ar + g + 8) * 36 + k8 + t + 4]);
            }
#pragma unroll
            for (int nt = 0; nt < 4; nt++) {
                int bc = wn + nt * 8;
                uint32_t b0 = fu(Bst[(bc + g) * 36 + k8 + t]);
                uint32_t b1 = fu(Bst[(bc + g) * 36 + k8 + t + 4]);
#pragma unroll
                for (int mt = 0; mt < 4; mt++)
                    mma8(acc[mt][nt], af[mt][0], af[mt][1], af[mt][2], af[mt][3],
                         b0, b1);
            }
        }
        __syncthreads();

        if (i + 2 < NK) {
            int kt = (i + 2) * GBK;
            uint32_t sa = sbase + (st * 2 * TILE_F) * 4;
            uint32_t sb = sa + TILE_F * 4;
#pragma unroll
            for (int it = 0; it < 4; it++) {
                cpa16(sa + (lrow[it] * 36 + lc4[it]) * 4,
                      &A[(size_t)(m0 + lrow[it]) * DM + kt + lc4[it]]);
                cpa16(sb + (lrow[it] * 36 + lc4[it]) * 4,
                      &Bt[(size_t)lrow[it] * DM + kt + lc4[it]]);
            }
        }
        CP_COMMIT();
    }

#pragma unroll
    for (int mt = 0; mt < 4; mt++) {
        int r0 = m0 + wm + mt * 16 + g;
#pragma unroll
        for (int nt = 0; nt < 4; nt++) {
            int col = c0 + wn + nt * 8 + 2 * t;
            float v0 = acc[mt][nt][0], v1 = acc[mt][nt][1];
            float v2 = acc[mt][nt][2], v3 = acc[mt][nt][3];
            if (HAS_BIAS) {
                float bv0 = bias[col], bv1 = bias[col + 1];
                v0 += bv0; v1 += bv1; v2 += bv0; v3 += bv1;
            }
            if (ROUND_OUT) {
                v0 = tf32r(v0); v1 = tf32r(v1); v2 = tf32r(v2); v3 = tf32r(v3);
            }
            *(float2*)&C[(size_t)r0 * DM + col] = make_float2(v0, v1);
            *(float2*)&C[(size_t)(r0 + 8) * DM + col] = make_float2(v2, v3);
        }
    }
}

// ====== flash attention v3: 128 queries / 8 warps per CTA ==================
// K/V tiles (64 keys) double-buffered via cp.async, shared by all 8 warps.
// Q fragments in registers. Heavy-diagonal blocks launch first.
#define QBLK 128
#define KP 68
#define VP 72
#define PP 68
#define ASMEM ((2 * (64 * KP + 64 * VP) + QBLK * PP) * sizeof(float))  // 106496

__global__ __launch_bounds__(256, 2) void attn_mma()
{
    extern __shared__ float sm[];
    float* Ksb = sm;                         // [2][64][KP]
    float* Vsb = sm + 2 * 64 * KP;           // [2][64][VP]
    float* Ps  = sm + 2 * (64 * KP + 64 * VP);   // [128][PP]

    const int qt = gridDim.x - 1 - blockIdx.x;   // heavy blocks first
    const int h = blockIdx.y, b = blockIdx.z;
    const int tid = threadIdx.x;
    const int warp = tid >> 5, lane = tid & 31;
    const int g = lane >> 2, t = lane & 3;
    const int q0 = qt * QBLK;
    const int qrow = warp * 16;
    const size_t headoff = (size_t)b * SEQ * DM + (size_t)h * HD;

    const uint32_t skb = smem_u32(Ksb);
    const uint32_t svb = smem_u32(Vsb);
    const float* kgl = g_k + headoff;
    const float* vgl = g_v + headoff;

    const int NT = 2 * qt + 2;   // k-tiles of 64 covering [0, q0+128)

    // prefetch K/V tile 0 into buffer 0 (256 threads, 4 chunks each per tile)
    {
#pragma unroll
        for (int it = 0; it < 4; it++) {
            int idx = tid + it * 256;
            int row = idx >> 4, c4 = (idx & 15) << 2;
            cpa16(skb + (row * KP + c4) * 4, &kgl[(size_t)row * DM + c4]);
            cpa16(svb + (row * VP + c4) * 4, &vgl[(size_t)row * DM + c4]);
        }
        CP_COMMIT();
    }

    // hoist Q fragments (loop-invariant)
    uint32_t qf[8][4];
    {
        const float* qbase = g_q + headoff + (size_t)(q0 + qrow + g) * DM;
#pragma unroll
        for (int ks = 0; ks < 8; ks++) {
            int k8 = ks * 8;
            qf[ks][0] = fu(qbase[k8 + t]);
            qf[ks][1] = fu(qbase[8 * (size_t)DM + k8 + t]);
            qf[ks][2] = fu(qbase[k8 + t + 4]);
            qf[ks][3] = fu(qbase[8 * (size_t)DM + k8 + t + 4]);
        }
    }

    float m0r = -1e30f, m1r = -1e30f, l0 = 0.f, l1 = 0.f;
    float oacc[8][4] = {};

    for (int jt = 0; jt < NT; jt++) {
        if (jt + 1 < NT) {
            const int nk0 = (jt + 1) * 64;
            const int nb = (jt + 1) & 1;
            uint32_t ka = skb + nb * 64 * KP * 4;
            uint32_t va = svb + nb * 64 * VP * 4;
#pragma unroll
            for (int it = 0; it < 4; it++) {
                int idx = tid + it * 256;
                int row = idx >> 4, c4 = (idx & 15) << 2;
                cpa16(ka + (row * KP + c4) * 4,
                      &kgl[(size_t)(nk0 + row) * DM + c4]);
                cpa16(va + (row * VP + c4) * 4,
                      &vgl[(size_t)(nk0 + row) * DM + c4]);
            }
        }
        CP_COMMIT();
        CP_WAIT1();
        __syncthreads();

        const float* Ks = Ksb + (jt & 1) * 64 * KP;
        const float* Vs = Vsb + (jt & 1) * 64 * VP;
        const int k0 = jt * 64;

        // S = Q @ K^T (warp: 16 x 64), Q frags from registers
        float sacc[8][4] = {};
#pragma unroll
        for (int ks = 0; ks < 8; ks++) {
            const int k8 = ks * 8;
#pragma unroll
            for (int nt = 0; nt < 8; nt++) {
                uint32_t b0 = fu(Ks[(nt * 8 + g) * KP + k8 + t]);
                uint32_t b1 = fu(Ks[(nt * 8 + g) * KP + k8 + t + 4]);
                mma8(sacc[nt], qf[ks][0], qf[ks][1], qf[ks][2], qf[ks][3],
                     b0, b1);
            }
        }

        const int r0 = q0 + qrow + g, r1 = r0 + 8;
        if (jt >= 2 * qt) {   // tiles overlapping the diagonal band
#pragma unroll
            for (int nt = 0; nt < 8; nt++) {
                int c0 = k0 + nt * 8 + 2 * t, c1 = c0 + 1;
                if (c0 > r0) sacc[nt][0] = -1e9f;
                if (c1 > r0) sacc[nt][1] = -1e9f;
                if (c0 > r1) sacc[nt][2] = -1e9f;
                if (c1 > r1) sacc[nt][3] = -1e9f;
            }
        }
#pragma unroll
        for (int nt = 0; nt < 8; nt++)
#pragma unroll
            for (int j = 0; j < 4; j++) sacc[nt][j] *= 0.125f;

        // online softmax
        float rm0 = -1e30f, rm1 = -1e30f;
#pragma unroll
        for (int nt = 0; nt < 8; nt++) {
            rm0 = fmaxf(rm0, fmaxf(sacc[nt][0], sacc[nt][1]));
            rm1 = fmaxf(rm1, fmaxf(sacc[nt][2], sacc[nt][3]));
        }
#pragma unroll
        for (int off = 1; off < 4; off <<= 1) {
            rm0 = fmaxf(rm0, __shfl_xor_sync(0xffffffffu, rm0, off));
            rm1 = fmaxf(rm1, __shfl_xor_sync(0xffffffffu, rm1, off));
        }
        float mn0 = fmaxf(m0r, rm0), mn1 = fmaxf(m1r, rm1);
        float al0 = __expf(m0r - mn0), al1 = __expf(m1r - mn1);
        float rs0 = 0.f, rs1 = 0.f;
#pragma unroll
        for (int nt = 0; nt < 8; nt++) {
            sacc[nt][0] = __expf(sacc[nt][0] - mn0);
            sacc[nt][1] = __expf(sacc[nt][1] - mn0);
            sacc[nt][2] = __expf(sacc[nt][2] - mn1);
            sacc[nt][3] = __expf(sacc[nt][3] - mn1);
            rs0 += sacc[nt][0] + sacc[nt][1];
            rs1 += sacc[nt][2] + sacc[nt][3];
        }
#pragma unroll
        for (int off = 1; off < 4; off <<= 1) {
            rs0 += __shfl_xor_sync(0xffffffffu, rs0, off);
            rs1 += __shfl_xor_sync(0xffffffffu, rs1, off);
        }
        l0 = l0 * al0 + rs0;
        l1 = l1 * al1 + rs1;
        m0r = mn0; m1r = mn1;
#pragma unroll
        for (int nt = 0; nt < 8; nt++) {
            oacc[nt][0] *= al0; oacc[nt][1] *= al0;
            oacc[nt][2] *= al1; oacc[nt][3] *= al1;
        }

        // P -> smem (warp-private rows), reload as A-fragments
#pragma unroll
        for (int nt = 0; nt < 8; nt++) {
            *(float2*)&Ps[(qrow + g) * PP + nt * 8 + 2 * t] =
                make_float2(tf32r(sacc[nt][0]), tf32r(sacc[nt][1]));
            *(float2*)&Ps[(qrow + g + 8) * PP + nt * 8 + 2 * t] =
                make_float2(tf32r(sacc[nt][2]), tf32r(sacc[nt][3]));
        }
        __syncwarp();

        // O += P @ V
#pragma unroll
        for (int ks = 0; ks < 8; ks++) {
            const int k8 = ks * 8;
            uint32_t a0 = fu(Ps[(qrow + g) * PP + k8 + t]);
            uint32_t a1 = fu(Ps[(qrow + g + 8) * PP + k8 + t]);
            uint32_t a2 = fu(Ps[(qrow + g) * PP + k8 + t + 4]);
            uint32_t a3 = fu(Ps[(qrow + g + 8) * PP + k8 + t + 4]);
#pragma unroll
            for (int nt = 0; nt < 8; nt++) {
                uint32_t b0 = fu(Vs[(k8 + t) * VP + nt * 8 + g]);
                uint32_t b1 = fu(Vs[(k8 + t + 4) * VP + nt * 8 + g]);
                mma8(oacc[nt], a0, a1, a2, a3, b0, b1);
            }
        }
        __syncthreads();
    }

    const float inv0 = 1.f / l0, inv1 = 1.f / l1;
    const int r0 = q0 + qrow + g, r1 = r0 + 8;
#pragma unroll
    for (int nt = 0; nt < 8; nt++) {
        int c = nt * 8 + 2 * t;
        *(float2*)&g_ctx[headoff + (size_t)r0 * DM + c] =
            make_float2(tf32r(oacc[nt][0] * inv0), tf32r(oacc[nt][1] * inv0));
        *(float2*)&g_ctx[headoff + (size_t)r1 * DM + c] =
            make_float2(tf32r(oacc[nt][2] * inv1), tf32r(oacc[nt][3] * inv1));
    }
}

// ---------------- launch ---------------------------------------------------
extern "C" void kernel_launch(void* const* d_in, const int* in_sizes, int n_in,
                              void* d_out, int out_size)
{
    const float* x  = (const float*)d_in[0];
    const float* Wq = (const float*)d_in[1];
    const float* Wk = (const float*)d_in[2];
    const float* Wv = (const float*)d_in[3];
    const float* Wo = (const float*)d_in[4];
    const float* bo = (const float*)d_in[5];
    float* out = (float*)d_out;

    float *gxr, *gctx, *gwt;
    cudaGetSymbolAddress((void**)&gxr, g_xr);
    cudaGetSymbolAddress((void**)&gctx, g_ctx);
    cudaGetSymbolAddress((void**)&gwt, g_wt);

    round_x<<<MTOT * DM / 4 / 256, 256>>>(x);
    transpose4<<<dim3(32, 32, 4), 256>>>(Wq, Wk, Wv, Wo);

    cudaFuncSetAttribute(gemm_cp<true, false, true>,
                         cudaFuncAttributeMaxDynamicSharedMemorySize, GSMEM);
    cudaFuncSetAttribute(gemm_cp<false, true, false>,
                         cudaFuncAttributeMaxDynamicSharedMemorySize, GSMEM);

    gemm_cp<true, false, true><<<dim3(3 * DM / GBN, MTOT / GBM), 256, GSMEM>>>(
        gxr, gwt, nullptr, nullptr);

    cudaFuncSetAttribute(attn_mma,
                         cudaFuncAttributeMaxDynamicSharedMemorySize, (int)ASMEM);
    attn_mma<<<dim3(SEQ / QBLK, NHEADS, BATCH), 256, ASMEM>>>();

    gemm_cp<false, true, false><<<dim3(DM / GBN, MTOT / GBM), 256, GSMEM>>>(
        gctx, gwt + 3 * (size_t)DM * DM, out, bo);
}

// round 8
// speedup vs baseline: 1.6037x; 1.6037x over previous
#include <cuda_runtime.h>
#include <cuda_fp16.h>
#include <math.h>
#include <stdint.h>

#define BATCH  2
#define SEQ    2048
#define DM     1024
#define NHEADS 16
#define HD     64
#define MTOT   (BATCH * SEQ)   // 4096

// ---------------- scratch (static device globals; no runtime alloc) --------
__device__ __half g_xh [MTOT * DM];      // x, fp16
__device__ __half g_wh [4 * DM * DM];    // transposed weights [mat][N][K], fp16
__device__ __half g_qh [MTOT * DM];      // Q [tok][dmodel]
__device__ __half g_kh [MTOT * DM];      // K [tok][dmodel]
__device__ __half g_vth[MTOT * DM];      // V transposed [b*h][d(64)][seq]
__device__ __half g_ctxh[MTOT * DM];     // attention output [tok][dmodel]

// ============================ helpers ======================================
__device__ __forceinline__ uint32_t fu(float x) { return __float_as_uint(x); }
__device__ __forceinline__ uint32_t h2u(float a, float b) {
    __half2 h = __floats2half2_rn(a, b);
    return *(uint32_t*)&h;
}
__device__ __forceinline__ uint32_t smem_u32(const void* p) {
    uint32_t a;
    asm("{ .reg .u64 t; cvta.to.shared.u64 t, %1; cvt.u32.u64 %0, t; }"
        : "=r"(a) : "l"(p));
    return a;
}
__device__ __forceinline__ void cpa16(uint32_t s, const void* g) {
    asm volatile("cp.async.ca.shared.global [%0], [%1], 16;" :: "r"(s), "l"(g));
}
#define CP_COMMIT() asm volatile("cp.async.commit_group;" ::: "memory")
#define CP_WAIT1()  asm volatile("cp.async.wait_group 1;" ::: "memory")

// D += A(16x16, row) * B(16x8, col), fp16 inputs, fp32 accum
__device__ __forceinline__ void mma16(float d[4], uint32_t a0, uint32_t a1,
                                      uint32_t a2, uint32_t a3,
                                      uint32_t b0, uint32_t b1) {
    asm volatile(
        "mma.sync.aligned.m16n8k16.row.col.f32.f16.f16.f32 "
        "{%0,%1,%2,%3}, {%4,%5,%6,%7}, {%8,%9}, {%0,%1,%2,%3};"
        : "+f"(d[0]), "+f"(d[1]), "+f"(d[2]), "+f"(d[3])
        : "r"(a0), "r"(a1), "r"(a2), "r"(a3), "r"(b0), "r"(b1));
}

// ================= prep kernels ============================================
__global__ __launch_bounds__(256) void cvt_x(const float* __restrict__ x) {
    int i = blockIdx.x * 256 + threadIdx.x;      // float4 index
    float4 v = ((const float4*)x)[i];
    uint2 o;
    o.x = h2u(v.x, v.y);
    o.y = h2u(v.z, v.w);
    ((uint2*)g_xh)[i] = o;
}

__global__ __launch_bounds__(256) void cvtT_w(
    const float* __restrict__ W0, const float* __restrict__ W1,
    const float* __restrict__ W2, const float* __restrict__ W3)
{
    __shared__ float t[32][33];
    const float* src = (blockIdx.z == 0) ? W0 : (blockIdx.z == 1) ? W1
                     : (blockIdx.z == 2) ? W2 : W3;
    __half* dst = g_wh + (size_t)blockIdx.z * DM * DM;
    int bk = blockIdx.y * 32, bn = blockIdx.x * 32;
    int tx = threadIdx.x & 31, ty = threadIdx.x >> 5;
#pragma unroll
    for (int i = 0; i < 4; i++)
        t[ty + 8 * i][tx] = src[(size_t)(bk + ty + 8 * i) * DM + bn + tx];
    __syncthreads();
#pragma unroll
    for (int i = 0; i < 4; i++)
        dst[(size_t)(bn + ty + 8 * i) * DM + bk + tx] =
            __float2half_rn(t[tx][ty + 8 * i]);
}

// ====== fp16 m16n8k16 GEMM, cp.async 2-stage ===============================
// BM=BN=128, BK=32; 256 threads = 8 warps (2x4); warp tile 64x32.
// smem pitch 40 halfs (80B): lane->bank map g*20+t all-distinct mod 32.
#define GBM 128
#define GBN 128
#define GBK 32
#define GP  40                         // halfs
#define GTILE_H (128 * GP)             // 5120 halfs per tile
#define GSMEM (2 * 2 * GTILE_H * 2)    // 40960 B

// MODE 0: fused QKV (A=g_xh, out half: Q,K normal; V transposed to g_vth)
// MODE 1: final (A=g_ctxh, out float + bias)
template<int MODE>
__global__ __launch_bounds__(256, 2) void gemm_h(
    const __half* __restrict__ A, const __half* __restrict__ BtBase,
    float* __restrict__ Cf, const float* __restrict__ bias)
{
    extern __shared__ __half gsmh[];

    const int tid = threadIdx.x;
    const int warp = tid >> 5, lane = tid & 31;
    const int g = lane >> 2, t = lane & 3;
    const int wm = (warp >> 2) * 64;
    const int wn = (warp & 3) * 32;
    const int m0 = blockIdx.y * GBM;
    const int n_glob = blockIdx.x * GBN;

    const __half* Bt = BtBase + (size_t)n_glob * DM;

    // load slots: 512 16B-chunks per tile, 2 per thread
    int lrow[2], lc8[2];
#pragma unroll
    for (int it = 0; it < 2; it++) {
        int idx = tid + it * 256;
        lrow[it] = idx >> 2;            // 0..127
        lc8[it]  = (idx & 3) << 3;      // 0,8,16,24
    }
    const uint32_t sbase = smem_u32(gsmh);

#pragma unroll
    for (int st = 0; st < 2; st++) {
        int kt = st * GBK;
        uint32_t sa = sbase + st * 2 * GTILE_H * 2;
        uint32_t sb = sa + GTILE_H * 2;
#pragma unroll
        for (int it = 0; it < 2; it++) {
            cpa16(sa + (lrow[it] * GP + lc8[it]) * 2,
                  &A[(size_t)(m0 + lrow[it]) * DM + kt + lc8[it]]);
            cpa16(sb + (lrow[it] * GP + lc8[it]) * 2,
                  &Bt[(size_t)lrow[it] * DM + kt + lc8[it]]);
        }
        CP_COMMIT();
    }

    float acc[4][4][4] = {};

    const int NK = DM / GBK;   // 32
    for (int i = 0; i < NK; i++) {
        CP_WAIT1();
        __syncthreads();
        const int st = i & 1;
        const __half* Ast = gsmh + st * 2 * GTILE_H;
        const __half* Bst = Ast + GTILE_H;

#pragma unroll
        for (int ks = 0; ks < 2; ks++) {
            const int k16 = ks * 16;
            uint32_t af[4][4];
#pragma unroll
            for (int mt = 0; mt < 4; mt++) {
                int ar = wm + mt * 16;
                af[mt][0] = *(const uint32_t*)(Ast + (ar + g) * GP + k16 + 2 * t);
                af[mt][1] = *(const uint32_t*)(Ast + (ar + g + 8) * GP + k16 + 2 * t);
                af[mt][2] = *(const uint32_t*)(Ast + (ar + g) * GP + k16 + 2 * t + 8);
                af[mt][3] = *(const uint32_t*)(Ast + (ar + g + 8) * GP + k16 + 2 * t + 8);
            }
#pragma unroll
            for (int nt = 0; nt < 4; nt++) {
                int bc = wn + nt * 8;
                uint32_t b0 = *(const uint32_t*)(Bst + (bc + g) * GP + k16 + 2 * t);
                uint32_t b1 = *(const uint32_t*)(Bst + (bc + g) * GP + k16 + 2 * t + 8);
#pragma unroll
                for (int mt = 0; mt < 4; mt++)
                    mma16(acc[mt][nt], af[mt][0], af[mt][1], af[mt][2], af[mt][3],
                          b0, b1);
            }
        }
        __syncthreads();

        if (i + 2 < NK) {
            int kt = (i + 2) * GBK;
            uint32_t sa = sbase + st * 2 * GTILE_H * 2;
            uint32_t sb = sa + GTILE_H * 2;
#pragma unroll
            for (int it = 0; it < 2; it++) {
                cpa16(sa + (lrow[it] * GP + lc8[it]) * 2,
                      &A[(size_t)(m0 + lrow[it]) * DM + kt + lc8[it]]);
                cpa16(sb + (lrow[it] * GP + lc8[it]) * 2,
                      &Bt[(size_t)lrow[it] * DM + kt + lc8[it]]);
            }
        }
        CP_COMMIT();
    }

    if (MODE == 0) {
        int mat = n_glob >> 10;               // 0=Q, 1=K, 2=V
        int c0 = n_glob & 1023;
        if (mat < 2) {
            __half* C = mat ? g_kh : g_qh;
#pragma unroll
            for (int mt = 0; mt < 4; mt++) {
                int r0 = m0 + wm + mt * 16 + g;
#pragma unroll
                for (int nt = 0; nt < 4; nt++) {
                    int col = c0 + wn + nt * 8 + 2 * t;
                    *(uint32_t*)&C[(size_t)r0 * DM + col] =
                        h2u(acc[mt][nt][0], acc[mt][nt][1]);
                    *(uint32_t*)&C[(size_t)(r0 + 8) * DM + col] =
                        h2u(acc[mt][nt][2], acc[mt][nt][3]);
                }
            }
        } else {
            // V: write transposed [b*16+h][d][tok]
#pragma unroll
            for (int mt = 0; mt < 4; mt++) {
                int r0 = m0 + wm + mt * 16 + g;
#pragma unroll
                for (int nt = 0; nt < 4; nt++) {
                    int dcol = c0 + wn + nt * 8 + 2 * t;   // 0..1023
                    int h = dcol >> 6, d = dcol & 63;
#pragma unroll
                    for (int rr = 0; rr < 2; rr++) {
                        int tok = r0 + rr * 8;
                        size_t base = ((size_t)((tok >> 11) * NHEADS + h) * HD + d)
                                      * SEQ + (tok & (SEQ - 1));
                        g_vth[base] = __float2half_rn(acc[mt][nt][rr * 2 + 0]);
                        g_vth[base + SEQ] = __float2half_rn(acc[mt][nt][rr * 2 + 1]);
                    }
                }
            }
        }
    } else {
#pragma unroll
        for (int mt = 0; mt < 4; mt++) {
            int r0 = m0 + wm + mt * 16 + g;
#pragma unroll
            for (int nt = 0; nt < 4; nt++) {
                int col = n_glob + wn + nt * 8 + 2 * t;
                float bv0 = bias[col], bv1 = bias[col + 1];
                *(float2*)&Cf[(size_t)r0 * DM + col] =
                    make_float2(acc[mt][nt][0] + bv0, acc[mt][nt][1] + bv1);
                *(float2*)&Cf[(size_t)(r0 + 8) * DM + col] =
                    make_float2(acc[mt][nt][2] + bv0, acc[mt][nt][3] + bv1);
            }
        }
    }
}

// ====== flash attention, fp16 m16n8k16 =====================================
// 128 queries / 8 warps / 256 threads. K and Vt tiles (64 keys) double-
// buffered via cp.async. Q frags in registers. pitch 72 halfs conflict-free.
#define QBLK 128
#define AP 72                                  // pitch in halfs
#define KTILE_H (64 * AP)                      // 4608 halfs
#define ASMEM ((4 * KTILE_H + QBLK * AP) * 2)  // 55296 B

__global__ __launch_bounds__(256, 2) void attn_h()
{
    extern __shared__ __half smh[];
    __half* Ksb = smh;                    // [2][64][AP]
    __half* Vsb = smh + 2 * KTILE_H;      // [2][64][AP]
    __half* Ps  = smh + 4 * KTILE_H;      // [128][AP]

    const int qt = gridDim.x - 1 - blockIdx.x;   // heavy blocks first
    const int h = blockIdx.y, b = blockIdx.z;
    const int tid = threadIdx.x;
    const int warp = tid >> 5, lane = tid & 31;
    const int g = lane >> 2, t = lane & 3;
    const int q0 = qt * QBLK;
    const int qrow = warp * 16;

    const __half* kgl = g_kh + (size_t)b * SEQ * DM + (size_t)h * HD;
    const __half* vtgl = g_vth + (size_t)(b * NHEADS + h) * HD * SEQ;

    const uint32_t skb = smem_u32(Ksb);
    const uint32_t svb = smem_u32(Vsb);

    const int NT = 2 * qt + 2;   // 64-key tiles covering [0, q0+128)

    // prefetch tile 0: K rows=keys, Vt rows=d; each row 64 halfs = 8 chunks
    {
#pragma unroll
        for (int it = 0; it < 2; it++) {
            int idx = tid + it * 256;
            int row = idx >> 3, c8 = (idx & 7) << 3;
            cpa16(skb + (row * AP + c8) * 2, &kgl[(size_t)row * DM + c8]);
            cpa16(svb + (row * AP + c8) * 2, &vtgl[(size_t)row * SEQ + c8]);
        }
        CP_COMMIT();
    }

    // hoist Q fragments (4 k-steps of 16)
    uint32_t qf[4][4];
    {
        const __half* qb = g_qh + (size_t)b * SEQ * DM + (size_t)h * HD
                         + (size_t)(q0 + qrow + g) * DM;
#pragma unroll
        for (int ks = 0; ks < 4; ks++) {
            int k16 = ks * 16;
            qf[ks][0] = *(const uint32_t*)(qb + k16 + 2 * t);
            qf[ks][1] = *(const uint32_t*)(qb + 8 * DM + k16 + 2 * t);
            qf[ks][2] = *(const uint32_t*)(qb + k16 + 2 * t + 8);
            qf[ks][3] = *(const uint32_t*)(qb + 8 * DM + k16 + 2 * t + 8);
        }
    }

    float m0r = -1e30f, m1r = -1e30f, l0 = 0.f, l1 = 0.f;
    float oacc[8][4] = {};

    for (int jt = 0; jt < NT; jt++) {
        if (jt + 1 < NT) {
            const int nk0 = (jt + 1) * 64;
            const int nb = (jt + 1) & 1;
            uint32_t ka = skb + nb * KTILE_H * 2;
            uint32_t va = svb + nb * KTILE_H * 2;
#pragma unroll
            for (int it = 0; it < 2; it++) {
                int idx = tid + it * 256;
                int row = idx >> 3, c8 = (idx & 7) << 3;
                cpa16(ka + (row * AP + c8) * 2,
                      &kgl[(size_t)(nk0 + row) * DM + c8]);
                cpa16(va + (row * AP + c8) * 2,
                      &vtgl[(size_t)row * SEQ + nk0 + c8]);
            }
        }
        CP_COMMIT();
        CP_WAIT1();
        __syncthreads();

        const __half* Ks = Ksb + (jt & 1) * KTILE_H;
        const __half* Vs = Vsb + (jt & 1) * KTILE_H;
        const int k0 = jt * 64;

        // S = Q @ K^T (warp: 16 x 64)
        float sacc[8][4] = {};
#pragma unroll
        for (int ks = 0; ks < 4; ks++) {
            const int k16 = ks * 16;
#pragma unroll
            for (int nt = 0; nt < 8; nt++) {
                uint32_t b0 = *(const uint32_t*)(Ks + (nt * 8 + g) * AP + k16 + 2 * t);
                uint32_t b1 = *(const uint32_t*)(Ks + (nt * 8 + g) * AP + k16 + 2 * t + 8);
                mma16(sacc[nt], qf[ks][0], qf[ks][1], qf[ks][2], qf[ks][3],
                      b0, b1);
            }
        }

        const int r0 = q0 + qrow + g, r1 = r0 + 8;
        if (jt >= 2 * qt) {   // diagonal band tiles
#pragma unroll
            for (int nt = 0; nt < 8; nt++) {
                int c0 = k0 + nt * 8 + 2 * t, c1 = c0 + 1;
                if (c0 > r0) sacc[nt][0] = -1e9f;
                if (c1 > r0) sacc[nt][1] = -1e9f;
                if (c0 > r1) sacc[nt][2] = -1e9f;
                if (c1 > r1) sacc[nt][3] = -1e9f;
            }
        }
#pragma unroll
        for (int nt = 0; nt < 8; nt++)
#pragma unroll
            for (int j = 0; j < 4; j++) sacc[nt][j] *= 0.125f;

        // online softmax
        float rm0 = -1e30f, rm1 = -1e30f;
#pragma unroll
        for (int nt = 0; nt < 8; nt++) {
            rm0 = fmaxf(rm0, fmaxf(sacc[nt][0], sacc[nt][1]));
            rm1 = fmaxf(rm1, fmaxf(sacc[nt][2], sacc[nt][3]));
        }
#pragma unroll
        for (int off = 1; off < 4; off <<= 1) {
            rm0 = fmaxf(rm0, __shfl_xor_sync(0xffffffffu, rm0, off));
            rm1 = fmaxf(rm1, __shfl_xor_sync(0xffffffffu, rm1, off));
        }
        float mn0 = fmaxf(m0r, rm0), mn1 = fmaxf(m1r, rm1);
        float al0 = __expf(m0r - mn0), al1 = __expf(m1r - mn1);
        float rs0 = 0.f, rs1 = 0.f;
#pragma unroll
        for (int nt = 0; nt < 8; nt++) {
            sacc[nt][0] = __expf(sacc[nt][0] - mn0);
            sacc[nt][1] = __expf(sacc[nt][1] - mn0);
            sacc[nt][2] = __expf(sacc[nt][2] - mn1);
            sacc[nt][3] = __expf(sacc[nt][3] - mn1);
            rs0 += sacc[nt][0] + sacc[nt][1];
            rs1 += sacc[nt][2] + sacc[nt][3];
        }
#pragma unroll
        for (int off = 1; off < 4; off <<= 1) {
            rs0 += __shfl_xor_sync(0xffffffffu, rs0, off);
            rs1 += __shfl_xor_sync(0xffffffffu, rs1, off);
        }
        l0 = l0 * al0 + rs0;
        l1 = l1 * al1 + rs1;
        m0r = mn0; m1r = mn1;
#pragma unroll
        for (int nt = 0; nt < 8; nt++) {
            oacc[nt][0] *= al0; oacc[nt][1] *= al0;
            oacc[nt][2] *= al1; oacc[nt][3] *= al1;
        }

        // P -> smem as half2 (warp-private rows)
#pragma unroll
        for (int nt = 0; nt < 8; nt++) {
            *(uint32_t*)(Ps + (qrow + g) * AP + nt * 8 + 2 * t) =
                h2u(sacc[nt][0], sacc[nt][1]);
            *(uint32_t*)(Ps + (qrow + g + 8) * AP + nt * 8 + 2 * t) =
                h2u(sacc[nt][2], sacc[nt][3]);
        }
        __syncwarp();

        // O += P @ V   (A=P row-major, B=Vt col-major over key)
#pragma unroll
        for (int ks = 0; ks < 4; ks++) {
            const int k16 = ks * 16;
            uint32_t a0 = *(const uint32_t*)(Ps + (qrow + g) * AP + k16 + 2 * t);
            uint32_t a1 = *(const uint32_t*)(Ps + (qrow + g + 8) * AP + k16 + 2 * t);
            uint32_t a2 = *(const uint32_t*)(Ps + (qrow + g) * AP + k16 + 2 * t + 8);
            uint32_t a3 = *(const uint32_t*)(Ps + (qrow + g + 8) * AP + k16 + 2 * t + 8);
#pragma unroll
            for (int nt = 0; nt < 8; nt++) {
                uint32_t b0 = *(const uint32_t*)(Vs + (nt * 8 + g) * AP + k16 + 2 * t);
                uint32_t b1 = *(const uint32_t*)(Vs + (nt * 8 + g) * AP + k16 + 2 * t + 8);
                mma16(oacc[nt], a0, a1, a2, a3, b0, b1);
            }
        }
        __syncthreads();
    }

    // normalize, write ctx (half)
    const float inv0 = 1.f / l0, inv1 = 1.f / l1;
    __half* ctx = g_ctxh + (size_t)b * SEQ * DM + (size_t)h * HD;
    const int r0 = q0 + qrow + g, r1 = r0 + 8;
#pragma unroll
    for (int nt = 0; nt < 8; nt++) {
        int c = nt * 8 + 2 * t;
        *(uint32_t*)&ctx[(size_t)r0 * DM + c] =
            h2u(oacc[nt][0] * inv0, oacc[nt][1] * inv0);
        *(uint32_t*)&ctx[(size_t)r1 * DM + c] =
            h2u(oacc[nt][2] * inv1, oacc[nt][3] * inv1);
    }
}

// ---------------- launch ---------------------------------------------------
extern "C" void kernel_launch(void* const* d_in, const int* in_sizes, int n_in,
                              void* d_out, int out_size)
{
    const float* x  = (const float*)d_in[0];
    const float* Wq = (const float*)d_in[1];
    const float* Wk = (const float*)d_in[2];
    const float* Wv = (const float*)d_in[3];
    const float* Wo = (const float*)d_in[4];
    const float* bo = (const float*)d_in[5];
    float* out = (float*)d_out;

    __half *gxh, *gwh, *gctxh;
    cudaGetSymbolAddress((void**)&gxh, g_xh);
    cudaGetSymbolAddress((void**)&gwh, g_wh);
    cudaGetSymbolAddress((void**)&gctxh, g_ctxh);

    cvt_x<<<MTOT * DM / 4 / 256, 256>>>(x);
    cvtT_w<<<dim3(32, 32, 4), 256>>>(Wq, Wk, Wv, Wo);

    cudaFuncSetAttribute(gemm_h<0>,
                         cudaFuncAttributeMaxDynamicSharedMemorySize, GSMEM);
    cudaFuncSetAttribute(gemm_h<1>,
                         cudaFuncAttributeMaxDynamicSharedMemorySize, GSMEM);

    // fused QKV: output columns [0, 3072)
    gemm_h<0><<<dim3(3 * DM / GBN, MTOT / GBM), 256, GSMEM>>>(
        gxh, gwh, nullptr, nullptr);

    cudaFuncSetAttribute(attn_h,
                         cudaFuncAttributeMaxDynamicSharedMemorySize, (int)ASMEM);
    attn_h<<<dim3(SEQ / QBLK, NHEADS, BATCH), 256, ASMEM>>>();

    gemm_h<1><<<dim3(DM / GBN, MTOT / GBM), 256, GSMEM>>>(
        gctxh, gwh + 3 * (size_t)DM * DM, out, bo);
}

// round 9
// speedup vs baseline: 1.8377x; 1.1460x over previous
#include <cuda_runtime.h>
#include <cuda_fp16.h>
#include <math.h>
#include <stdint.h>

#define BATCH  2
#define SEQ    2048
#define DM     1024
#define NHEADS 16
#define HD     64
#define MTOT   (BATCH * SEQ)   // 4096

// ---------------- scratch (static device globals; no runtime alloc) --------
__device__ __half g_xh [MTOT * DM];      // x, fp16
__device__ __half g_wh [4 * DM * DM];    // transposed weights [mat][N][K], fp16
__device__ __half g_qh [MTOT * DM];      // Q [tok][dmodel], PRESCALED by 0.125
__device__ __half g_kh [MTOT * DM];      // K [tok][dmodel]
__device__ __half g_vth[MTOT * DM];      // V transposed [b*h][d(64)][seq]
__device__ __half g_ctxh[MTOT * DM];     // attention output [tok][dmodel]

// ============================ helpers ======================================
__device__ __forceinline__ uint32_t h2u(float a, float b) {
    __half2 h = __floats2half2_rn(a, b);
    return *(uint32_t*)&h;
}
__device__ __forceinline__ uint32_t smem_u32(const void* p) {
    uint32_t a;
    asm("{ .reg .u64 t; cvta.to.shared.u64 t, %1; cvt.u32.u64 %0, t; }"
        : "=r"(a) : "l"(p));
    return a;
}
__device__ __forceinline__ void cpa16(uint32_t s, const void* g) {
    asm volatile("cp.async.ca.shared.global [%0], [%1], 16;" :: "r"(s), "l"(g));
}
#define CP_COMMIT() asm volatile("cp.async.commit_group;" ::: "memory")
#define CP_WAIT1()  asm volatile("cp.async.wait_group 1;" ::: "memory")

__device__ __forceinline__ void ldsm4(uint32_t& r0, uint32_t& r1,
                                      uint32_t& r2, uint32_t& r3, uint32_t a) {
    asm volatile("ldmatrix.sync.aligned.m8n8.x4.shared.b16 {%0,%1,%2,%3}, [%4];"
                 : "=r"(r0), "=r"(r1), "=r"(r2), "=r"(r3) : "r"(a));
}
__device__ __forceinline__ void ldsm2(uint32_t& r0, uint32_t& r1, uint32_t a) {
    asm volatile("ldmatrix.sync.aligned.m8n8.x2.shared.b16 {%0,%1}, [%2];"
                 : "=r"(r0), "=r"(r1) : "r"(a));
}

// D += A(16x16, row) * B(16x8, col), fp16 inputs, fp32 accum
__device__ __forceinline__ void mma16(float d[4], uint32_t a0, uint32_t a1,
                                      uint32_t a2, uint32_t a3,
                                      uint32_t b0, uint32_t b1) {
    asm volatile(
        "mma.sync.aligned.m16n8k16.row.col.f32.f16.f16.f32 "
        "{%0,%1,%2,%3}, {%4,%5,%6,%7}, {%8,%9}, {%0,%1,%2,%3};"
        : "+f"(d[0]), "+f"(d[1]), "+f"(d[2]), "+f"(d[3])
        : "r"(a0), "r"(a1), "r"(a2), "r"(a3), "r"(b0), "r"(b1));
}

// ================= prep kernels ============================================
__global__ __launch_bounds__(256) void cvt_x(const float* __restrict__ x) {
    int i = blockIdx.x * 256 + threadIdx.x;
    float4 v = ((const float4*)x)[i];
    uint2 o;
    o.x = h2u(v.x, v.y);
    o.y = h2u(v.z, v.w);
    ((uint2*)g_xh)[i] = o;
}

__global__ __launch_bounds__(256) void cvtT_w(
    const float* __restrict__ W0, const float* __restrict__ W1,
    const float* __restrict__ W2, const float* __restrict__ W3)
{
    __shared__ float t[32][33];
    const float* src = (blockIdx.z == 0) ? W0 : (blockIdx.z == 1) ? W1
                     : (blockIdx.z == 2) ? W2 : W3;
    __half* dst = g_wh + (size_t)blockIdx.z * DM * DM;
    int bk = blockIdx.y * 32, bn = blockIdx.x * 32;
    int tx = threadIdx.x & 31, ty = threadIdx.x >> 5;
#pragma unroll
    for (int i = 0; i < 4; i++)
        t[ty + 8 * i][tx] = src[(size_t)(bk + ty + 8 * i) * DM + bn + tx];
    __syncthreads();
#pragma unroll
    for (int i = 0; i < 4; i++)
        dst[(size_t)(bn + ty + 8 * i) * DM + bk + tx] =
            __float2half_rn(t[tx][ty + 8 * i]);
}

// ====== fp16 m16n8k16 GEMM, cp.async 2-stage, ldmatrix fragments ===========
#define GBM 128
#define GBN 128
#define GBK 32
#define GP  40                         // pitch in halfs (80 B, 16B-multiple)
#define GTILE_H (128 * GP)
#define GSMEM (2 * 2 * GTILE_H * 2)    // 40960 B

// MODE 0: fused QKV (Q prescaled 0.125; V transposed to g_vth)
// MODE 1: final (out float + bias)
template<int MODE>
__global__ __launch_bounds__(256, 2) void gemm_h(
    const __half* __restrict__ A, const __half* __restrict__ BtBase,
    float* __restrict__ Cf, const float* __restrict__ bias)
{
    extern __shared__ __half gsmh[];

    const int tid = threadIdx.x;
    const int warp = tid >> 5, lane = tid & 31;
    const int g = lane >> 2, t = lane & 3;
    const int wm = (warp >> 2) * 64;
    const int wn = (warp & 3) * 32;
    const int m0 = blockIdx.y * GBM;
    const int n_glob = blockIdx.x * GBN;

    const __half* Bt = BtBase + (size_t)n_glob * DM;

    // ldmatrix lane offsets (halfs)
    const int lr = lane & 7;
    const int lqA = lane >> 3;                       // A x4: 4 tiles
    const uint32_t lmA = (uint32_t)((((lqA & 1) * 8 + lr) * GP + (lqA >> 1) * 8) * 2);
    const int lqB = (lane >> 3) & 1;                 // B x2: 2 tiles (lanes 0-15)
    const uint32_t lmB = (uint32_t)((lr * GP + lqB * 8) * 2);

    int lrow[2], lc8[2];
#pragma unroll
    for (int it = 0; it < 2; it++) {
        int idx = tid + it * 256;
        lrow[it] = idx >> 2;
        lc8[it]  = (idx & 3) << 3;
    }
    const uint32_t sbase = smem_u32(gsmh);

#pragma unroll
    for (int st = 0; st < 2; st++) {
        int kt = st * GBK;
        uint32_t sa = sbase + st * 2 * GTILE_H * 2;
        uint32_t sb = sa + GTILE_H * 2;
#pragma unroll
        for (int it = 0; it < 2; it++) {
            cpa16(sa + (lrow[it] * GP + lc8[it]) * 2,
                  &A[(size_t)(m0 + lrow[it]) * DM + kt + lc8[it]]);
            cpa16(sb + (lrow[it] * GP + lc8[it]) * 2,
                  &Bt[(size_t)lrow[it] * DM + kt + lc8[it]]);
        }
        CP_COMMIT();
    }

    float acc[4][4][4] = {};

    const int NK = DM / GBK;
    for (int i = 0; i < NK; i++) {
        CP_WAIT1();
        __syncthreads();
        const int st = i & 1;
        const uint32_t aA = sbase + st * 2 * GTILE_H * 2;
        const uint32_t aB = aA + GTILE_H * 2;

#pragma unroll
        for (int ks = 0; ks < 2; ks++) {
            const int k16 = ks * 16;
            uint32_t af[4][4];
#pragma unroll
            for (int mt = 0; mt < 4; mt++)
                ldsm4(af[mt][0], af[mt][1], af[mt][2], af[mt][3],
                      aA + (uint32_t)(((wm + mt * 16) * GP + k16) * 2) + lmA);
#pragma unroll
            for (int nt = 0; nt < 4; nt++) {
                uint32_t b0, b1;
                ldsm2(b0, b1,
                      aB + (uint32_t)(((wn + nt * 8) * GP + k16) * 2) + lmB);
#pragma unroll
                for (int mt = 0; mt < 4; mt++)
                    mma16(acc[mt][nt], af[mt][0], af[mt][1], af[mt][2], af[mt][3],
                          b0, b1);
            }
        }
        __syncthreads();

        if (i + 2 < NK) {
            int kt = (i + 2) * GBK;
            uint32_t sa = sbase + st * 2 * GTILE_H * 2;
            uint32_t sb = sa + GTILE_H * 2;
#pragma unroll
            for (int it = 0; it < 2; it++) {
                cpa16(sa + (lrow[it] * GP + lc8[it]) * 2,
                      &A[(size_t)(m0 + lrow[it]) * DM + kt + lc8[it]]);
                cpa16(sb + (lrow[it] * GP + lc8[it]) * 2,
                      &Bt[(size_t)lrow[it] * DM + kt + lc8[it]]);
            }
        }
        CP_COMMIT();
    }

    if (MODE == 0) {
        int mat = n_glob >> 10;               // 0=Q, 1=K, 2=V
        int c0 = n_glob & 1023;
        if (mat < 2) {
            __half* C = mat ? g_kh : g_qh;
            const float s = mat ? 1.0f : 0.125f;   // prescale Q by 1/sqrt(64)
#pragma unroll
            for (int mt = 0; mt < 4; mt++) {
                int r0 = m0 + wm + mt * 16 + g;
#pragma unroll
                for (int nt = 0; nt < 4; nt++) {
                    int col = c0 + wn + nt * 8 + 2 * t;
                    *(uint32_t*)&C[(size_t)r0 * DM + col] =
                        h2u(acc[mt][nt][0] * s, acc[mt][nt][1] * s);
                    *(uint32_t*)&C[(size_t)(r0 + 8) * DM + col] =
                        h2u(acc[mt][nt][2] * s, acc[mt][nt][3] * s);
                }
            }
        } else {
#pragma unroll
            for (int mt = 0; mt < 4; mt++) {
                int r0 = m0 + wm + mt * 16 + g;
#pragma unroll
                for (int nt = 0; nt < 4; nt++) {
                    int dcol = c0 + wn + nt * 8 + 2 * t;
                    int h = dcol >> 6, d = dcol & 63;
#pragma unroll
                    for (int rr = 0; rr < 2; rr++) {
                        int tok = r0 + rr * 8;
                        size_t base = ((size_t)((tok >> 11) * NHEADS + h) * HD + d)
                                      * SEQ + (tok & (SEQ - 1));
                        g_vth[base] = __float2half_rn(acc[mt][nt][rr * 2 + 0]);
                        g_vth[base + SEQ] = __float2half_rn(acc[mt][nt][rr * 2 + 1]);
                    }
                }
            }
        }
    } else {
#pragma unroll
        for (int mt = 0; mt < 4; mt++) {
            int r0 = m0 + wm + mt * 16 + g;
#pragma unroll
            for (int nt = 0; nt < 4; nt++) {
                int col = n_glob + wn + nt * 8 + 2 * t;
                float bv0 = bias[col], bv1 = bias[col + 1];
                *(float2*)&Cf[(size_t)r0 * DM + col] =
                    make_float2(acc[mt][nt][0] + bv0, acc[mt][nt][1] + bv1);
                *(float2*)&Cf[(size_t)(r0 + 8) * DM + col] =
                    make_float2(acc[mt][nt][2] + bv0, acc[mt][nt][3] + bv1);
            }
        }
    }
}

// ====== flash attention: P in registers, ldmatrix K/V ======================
// 128 queries / 8 warps / 256 threads. K and Vt tiles (64 keys) double-
// buffered via cp.async. Q frags in regs (prescaled). No P smem.
#define QBLK 128
#define AP 72                        // pitch in halfs (144 B, 16B-multiple)
#define KTILE_H (64 * AP)
#define ASMEM (4 * KTILE_H * 2)      // 36864 B

__global__ __launch_bounds__(256, 2) void attn_h()
{
    extern __shared__ __half smh[];
    __half* Ksb = smh;                    // [2][64][AP] (rows = key)
    __half* Vsb = smh + 2 * KTILE_H;      // [2][64][AP] (rows = d)

    const int qt = gridDim.x - 1 - blockIdx.x;   // heavy blocks first
    const int h = blockIdx.y, b = blockIdx.z;
    const int tid = threadIdx.x;
    const int warp = tid >> 5, lane = tid & 31;
    const int g = lane >> 2, t = lane & 3;
    const int q0 = qt * QBLK;
    const int qrow = warp * 16;

    const __half* kgl = g_kh + (size_t)b * SEQ * DM + (size_t)h * HD;
    const __half* vtgl = g_vth + (size_t)(b * NHEADS + h) * HD * SEQ;

    const uint32_t skb = smem_u32(Ksb);
    const uint32_t svb = smem_u32(Vsb);

    // ldmatrix x4 lane offset: tiles (rows+0 klo),(rows+0 khi),(rows+8 klo),(rows+8 khi)
    const int lr = lane & 7, lq = lane >> 3;
    const uint32_t lmB = (uint32_t)(((((lq >> 1) & 1) * 8 + lr) * AP + (lq & 1) * 8) * 2);

    const int NT = 2 * qt + 2;

    {
#pragma unroll
        for (int it = 0; it < 2; it++) {
            int idx = tid + it * 256;
            int row = idx >> 3, c8 = (idx & 7) << 3;
            cpa16(skb + (row * AP + c8) * 2, &kgl[(size_t)row * DM + c8]);
            cpa16(svb + (row * AP + c8) * 2, &vtgl[(size_t)row * SEQ + c8]);
        }
        CP_COMMIT();
    }

    // hoist Q fragments (Q already scaled by 0.125)
    uint32_t qf[4][4];
    {
        const __half* qb = g_qh + (size_t)b * SEQ * DM + (size_t)h * HD
                         + (size_t)(q0 + qrow + g) * DM;
#pragma unroll
        for (int ks = 0; ks < 4; ks++) {
            int k16 = ks * 16;
            qf[ks][0] = *(const uint32_t*)(qb + k16 + 2 * t);
            qf[ks][1] = *(const uint32_t*)(qb + 8 * DM + k16 + 2 * t);
            qf[ks][2] = *(const uint32_t*)(qb + k16 + 2 * t + 8);
            qf[ks][3] = *(const uint32_t*)(qb + 8 * DM + k16 + 2 * t + 8);
        }
    }

    float m0r = -1e30f, m1r = -1e30f, l0 = 0.f, l1 = 0.f;
    float oacc[8][4] = {};

    for (int jt = 0; jt < NT; jt++) {
        if (jt + 1 < NT) {
            const int nk0 = (jt + 1) * 64;
            const int nb = (jt + 1) & 1;
            uint32_t ka = skb + nb * KTILE_H * 2;
            uint32_t va = svb + nb * KTILE_H * 2;
#pragma unroll
            for (int it = 0; it < 2; it++) {
                int idx = tid + it * 256;
                int row = idx >> 3, c8 = (idx & 7) << 3;
                cpa16(ka + (row * AP + c8) * 2,
                      &kgl[(size_t)(nk0 + row) * DM + c8]);
                cpa16(va + (row * AP + c8) * 2,
                      &vtgl[(size_t)row * SEQ + nk0 + c8]);
            }
        }
        CP_COMMIT();
        CP_WAIT1();
        __syncthreads();

        const uint32_t ksa = skb + (jt & 1) * KTILE_H * 2;
        const uint32_t vsa = svb + (jt & 1) * KTILE_H * 2;
        const int k0 = jt * 64;

        // S = Q @ K^T: ldmatrix x4 gives B-frags for 2 consecutive n-tiles
        float sacc[8][4] = {};
#pragma unroll
        for (int ks = 0; ks < 4; ks++) {
            const int k16 = ks * 16;
#pragma unroll
            for (int ntp = 0; ntp < 4; ntp++) {
                uint32_t b0, b1, b2, b3;
                ldsm4(b0, b1, b2, b3,
                      ksa + (uint32_t)((ntp * 16 * AP + k16) * 2) + lmB);
                mma16(sacc[2 * ntp], qf[ks][0], qf[ks][1], qf[ks][2], qf[ks][3],
                      b0, b1);
                mma16(sacc[2 * ntp + 1], qf[ks][0], qf[ks][1], qf[ks][2], qf[ks][3],
                      b2, b3);
            }
        }

        const int r0 = q0 + qrow + g, r1 = r0 + 8;
        if (jt >= 2 * qt) {   // diagonal band (s already scaled via Q)
#pragma unroll
            for (int nt = 0; nt < 8; nt++) {
                int c0 = k0 + nt * 8 + 2 * t, c1 = c0 + 1;
                if (c0 > r0) sacc[nt][0] = -1e9f;
                if (c1 > r0) sacc[nt][1] = -1e9f;
                if (c0 > r1) sacc[nt][2] = -1e9f;
                if (c1 > r1) sacc[nt][3] = -1e9f;
            }
        }

        // online softmax
        float rm0 = -1e30f, rm1 = -1e30f;
#pragma unroll
        for (int nt = 0; nt < 8; nt++) {
            rm0 = fmaxf(rm0, fmaxf(sacc[nt][0], sacc[nt][1]));
            rm1 = fmaxf(rm1, fmaxf(sacc[nt][2], sacc[nt][3]));
        }
#pragma unroll
        for (int off = 1; off < 4; off <<= 1) {
            rm0 = fmaxf(rm0, __shfl_xor_sync(0xffffffffu, rm0, off));
            rm1 = fmaxf(rm1, __shfl_xor_sync(0xffffffffu, rm1, off));
        }
        float mn0 = fmaxf(m0r, rm0), mn1 = fmaxf(m1r, rm1);
        float al0 = __expf(m0r - mn0), al1 = __expf(m1r - mn1);
        float rs0 = 0.f, rs1 = 0.f;
#pragma unroll
        for (int nt = 0; nt < 8; nt++) {
            sacc[nt][0] = __expf(sacc[nt][0] - mn0);
            sacc[nt][1] = __expf(sacc[nt][1] - mn0);
            sacc[nt][2] = __expf(sacc[nt][2] - mn1);
            sacc[nt][3] = __expf(sacc[nt][3] - mn1);
            rs0 += sacc[nt][0] + sacc[nt][1];
            rs1 += sacc[nt][2] + sacc[nt][3];
        }
#pragma unroll
        for (int off = 1; off < 4; off <<= 1) {
            rs0 += __shfl_xor_sync(0xffffffffu, rs0, off);
            rs1 += __shfl_xor_sync(0xffffffffu, rs1, off);
        }
        l0 = l0 * al0 + rs0;
        l1 = l1 * al1 + rs1;
        m0r = mn0; m1r = mn1;
#pragma unroll
        for (int nt = 0; nt < 8; nt++) {
            oacc[nt][0] *= al0; oacc[nt][1] *= al0;
            oacc[nt][2] *= al1; oacc[nt][3] *= al1;
        }

        // P -> A-fragments directly in registers (C-frag == A-frag layout)
        uint32_t pa[4][4];
#pragma unroll
        for (int ksp = 0; ksp < 4; ksp++) {
            pa[ksp][0] = h2u(sacc[2 * ksp][0], sacc[2 * ksp][1]);
            pa[ksp][1] = h2u(sacc[2 * ksp][2], sacc[2 * ksp][3]);
            pa[ksp][2] = h2u(sacc[2 * ksp + 1][0], sacc[2 * ksp + 1][1]);
            pa[ksp][3] = h2u(sacc[2 * ksp + 1][2], sacc[2 * ksp + 1][3]);
        }

        // O += P @ V: Vt rows = d, cols = key
#pragma unroll
        for (int ksp = 0; ksp < 4; ksp++) {
            const int k16 = ksp * 16;
#pragma unroll
            for (int ntd = 0; ntd < 4; ntd++) {
                uint32_t v0, v1, v2, v3;
                ldsm4(v0, v1, v2, v3,
                      vsa + (uint32_t)((ntd * 16 * AP + k16) * 2) + lmB);
                mma16(oacc[2 * ntd], pa[ksp][0], pa[ksp][1], pa[ksp][2],
                      pa[ksp][3], v0, v1);
                mma16(oacc[2 * ntd + 1], pa[ksp][0], pa[ksp][1], pa[ksp][2],
                      pa[ksp][3], v2, v3);
            }
        }
        __syncthreads();
    }

    // normalize, write ctx (half)
    const float inv0 = 1.f / l0, inv1 = 1.f / l1;
    __half* ctx = g_ctxh + (size_t)b * SEQ * DM + (size_t)h * HD;
    const int r0 = q0 + qrow + g, r1 = r0 + 8;
#pragma unroll
    for (int nt = 0; nt < 8; nt++) {
        int c = nt * 8 + 2 * t;
        *(uint32_t*)&ctx[(size_t)r0 * DM + c] =
            h2u(oacc[nt][0] * inv0, oacc[nt][1] * inv0);
        *(uint32_t*)&ctx[(size_t)r1 * DM + c] =
            h2u(oacc[nt][2] * inv1, oacc[nt][3] * inv1);
    }
}

// ---------------- launch ---------------------------------------------------
extern "C" void kernel_launch(void* const* d_in, const int* in_sizes, int n_in,
                              void* d_out, int out_size)
{
    const float* x  = (const float*)d_in[0];
    const float* Wq = (const float*)d_in[1];
    const float* Wk = (const float*)d_in[2];
    const float* Wv = (const float*)d_in[3];
    const float* Wo = (const float*)d_in[4];
    const float* bo = (const float*)d_in[5];
    float* out = (float*)d_out;

    __half *gxh, *gwh, *gctxh;
    cudaGetSymbolAddress((void**)&gxh, g_xh);
    cudaGetSymbolAddress((void**)&gwh, g_wh);
    cudaGetSymbolAddress((void**)&gctxh, g_ctxh);

    cvt_x<<<MTOT * DM / 4 / 256, 256>>>(x);
    cvtT_w<<<dim3(32, 32, 4), 256>>>(Wq, Wk, Wv, Wo);

    cudaFuncSetAttribute(gemm_h<0>,
                         cudaFuncAttributeMaxDynamicSharedMemorySize, GSMEM);
    cudaFuncSetAttribute(gemm_h<1>,
                         cudaFuncAttributeMaxDynamicSharedMemorySize, GSMEM);

    gemm_h<0><<<dim3(3 * DM / GBN, MTOT / GBM), 256, GSMEM>>>(
        gxh, gwh, nullptr, nullptr);

    cudaFuncSetAttribute(attn_h,
                         cudaFuncAttributeMaxDynamicSharedMemorySize, (int)ASMEM);
    attn_h<<<dim3(SEQ / QBLK, NHEADS, BATCH), 256, ASMEM>>>();

    gemm_h<1><<<dim3(DM / GBN, MTOT / GBM), 256, GSMEM>>>(
        gctxh, gwh + 3 * (size_t)DM * DM, out, bo);
}